// round 14
// baseline (speedup 1.0000x reference)
#include <cuda_runtime.h>
#include <cuda_fp16.h>
#include <cstdint>
#include <math.h>

// SelfAttention B=8, C=64, N=4096 fp32. v9: m-split for 16 warps/SM.
//  fp16 m16n8k16 + ldmatrix, fp16 globals (K pre-scaled 0.125*log2e),
//  ex2.f16x2 softmax, ones-column-MMA rowsum.
//  Warp = 32 n-rows x HALF the m-tile (wm in {0,1}); pairs combine partial
//  O/rowsum in the epilogue. S chunked (16 m at a time: G1->exp->G2) and K
//  fragments reloaded from smem so regs fit 128 -> 2 CTAs x 256 thr / SM
//  = 4 warps/SMSP to hide exp/LDSM latency (v7/v8 had only 2).

#define NSEQ 4096
#define CD   64
#define TOT  (8 * CD * NSEQ)

#define STR    272             // universal fp16 row stride (256B data + 16 pad)
#define OFF_KS 0               // K [c=64][n=128] fp16, 17408 B
#define STG0   17408           // 2 stages, each Q(17408)+V(17408)
#define STGSZ  34816
#define STGV   17408
#define SMEM_TOTAL 87040       // x2 CTAs = 174080 <= 228KB
#define OSTB   528             // epilogue fp32 O staging stride (offset 0)
#define RSOFF  33792           // rowsum partials [2][128] f32 (after 64*528 Os)

#define ONES2 0x3C003C00u      // f16x2 {1.0, 1.0}

__device__ __align__(16) __half gK[TOT];
__device__ __align__(16) __half gQ[TOT];
__device__ __align__(16) __half gV[TOT];

static __device__ __forceinline__ uint32_t smem_u32(const void* p) {
    uint32_t a;
    asm("{ .reg .u64 t; cvta.to.shared.u64 t, %1; cvt.u32.u64 %0, t; }" : "=r"(a) : "l"(p));
    return a;
}
static __device__ __forceinline__ uint32_t pkh2(float lo, float hi) {
    uint32_t d;
    asm("cvt.rn.f16x2.f32 %0, %1, %2;" : "=r"(d) : "f"(hi), "f"(lo));
    return d;
}
static __device__ __forceinline__ uint32_t ex2h2(uint32_t x) {
    uint32_t d;
    asm("ex2.approx.f16x2 %0, %1;" : "=r"(d) : "r"(x));
    return d;
}

#define CP16(dst, src) asm volatile("cp.async.cg.shared.global [%0], [%1], 16;" :: "r"(dst), "l"(src) : "memory")
#define CP_COMMIT()    asm volatile("cp.async.commit_group;" ::: "memory")
#define CP_WAIT(n)     asm volatile("cp.async.wait_group %0;" :: "n"(n) : "memory")

#define LDSM4(r0,r1,r2,r3,a) \
    asm volatile("ldmatrix.sync.aligned.m8n8.x4.shared.b16 {%0,%1,%2,%3}, [%4];" \
        : "=r"(r0),"=r"(r1),"=r"(r2),"=r"(r3) : "r"(a))
#define LDSM4T(r0,r1,r2,r3,a) \
    asm volatile("ldmatrix.sync.aligned.m8n8.x4.trans.shared.b16 {%0,%1,%2,%3}, [%4];" \
        : "=r"(r0),"=r"(r1),"=r"(r2),"=r"(r3) : "r"(a))

#define MMA16(d, a0, a1, a2, a3, b0, b1)                                         \
    asm volatile("mma.sync.aligned.m16n8k16.row.col.f32.f16.f16.f32 "            \
        "{%0,%1,%2,%3}, {%4,%5,%6,%7}, {%8,%9}, {%0,%1,%2,%3};"                  \
        : "+f"((d)[0]), "+f"((d)[1]), "+f"((d)[2]), "+f"((d)[3])                 \
        : "r"(a0), "r"(a1), "r"(a2), "r"(a3), "r"(b0), "r"(b1))

// ---- kernel 1: fp32 -> fp16 (K pre-scaled by 0.125*log2 e) ----
__global__ __launch_bounds__(256)
void cvt_to_f16(const float* __restrict__ K, const float* __restrict__ Q,
                const float* __restrict__ V)
{
    const int i = (blockIdx.x * 256 + threadIdx.x) * 8;
    const float sc = (blockIdx.y == 0) ? 0.18033688011112042f : 1.0f;
    const float* src = (blockIdx.y == 0) ? K : (blockIdx.y == 1) ? Q : V;
    __half* dst = (blockIdx.y == 0) ? gK : (blockIdx.y == 1) ? gQ : gV;
    float4 a = *(const float4*)(src + i);
    float4 b = *(const float4*)(src + i + 4);
    *(uint4*)(dst + i) = make_uint4(pkh2(a.x * sc, a.y * sc), pkh2(a.z * sc, a.w * sc),
                                    pkh2(b.x * sc, b.y * sc), pkh2(b.z * sc, b.w * sc));
}

// ---- kernel 2: attention, 256-thread CTA, 2 CTAs/SM (16 warps/SM) ----
__global__ __launch_bounds__(256, 2)
void attn_mma_v9(float* __restrict__ Out)
{
    extern __shared__ char smem[];
    const uint32_t sb = smem_u32(smem);
    const int tid  = threadIdx.x;
    const int wid  = tid >> 5, lane = tid & 31;
    const int g    = lane >> 2, tig = lane & 3;
    const int wn   = wid & 3,  wm  = wid >> 2;  // 4 n-groups x 2 m-halves
    const int nw0  = wn * 32;                   // warp's 32-row block
    const uint32_t mhb = wm * 128;              // m-half byte offset (64 m * 2B)
    const int b    = blockIdx.y, n0 = blockIdx.x * 128;
    const size_t base = (size_t)b * CD * NSEQ;
    const __half* kh = gK + base;
    const __half* qh = gQ + base;
    const __half* vh = gV + base;

    const int cc = tid >> 4, jc = tid & 15;     // loader: 16 c-rows/pass

    // ---- prologue: K tile [c=64][n=128] + tile 0 Q/V (one cp group) ----
    #pragma unroll
    for (int i = 0; i < 4; ++i) {
        int c = cc + i * 16;
        CP16(sb + OFF_KS + c * STR + jc * 16, kh + (size_t)c * NSEQ + n0 + jc * 8);
        CP16(sb + STG0 + c * STR + jc * 16, qh + (size_t)c * NSEQ + jc * 8);
        CP16(sb + STG0 + STGV + c * STR + jc * 16, vh + (size_t)c * NSEQ + jc * 8);
    }
    CP_COMMIT();

    float o[2][8][4];                // O partial: [nblk][ct][frag]
    float ors[2][4];                 // rowsum partial via ones-MMA
    #pragma unroll
    for (int nb = 0; nb < 2; ++nb) {
        #pragma unroll
        for (int e = 0; e < 4; ++e) ors[nb][e] = 0.f;
        #pragma unroll
        for (int ct = 0; ct < 8; ++ct)
            #pragma unroll
            for (int e = 0; e < 4; ++e) o[nb][ct][e] = 0.f;
    }

    const uint32_t kaddr = sb + OFF_KS + ((lane & 7) + ((lane & 16) ? 8 : 0)) * STR
                         + (nw0 + ((lane & 8) ? 8 : 0)) * 2;
    const uint32_t qbase = ((lane & 7) + ((lane & 8) ? 8 : 0)) * STR
                         + ((lane & 16) ? 16 : 0) + mhb;
    const uint32_t vbase = ((lane & 7) + ((lane & 16) ? 8 : 0)) * STR
                         + ((lane & 8) ? 16 : 0) + mhb;

    CP_WAIT(0);
    __syncthreads();

    for (int t = 0; t < 32; ++t) {
        const uint32_t qs = sb + STG0 + (uint32_t)(t & 1) * STGSZ;
        const uint32_t vs = qs + STGV;

        if (t > 0) { CP_WAIT(0); __syncthreads(); }   // tile t arrived; other buf free

        if (t + 1 < 32) {            // prefetch tile t+1 into the other stage
            const uint32_t so = sb + STG0 + (uint32_t)((t + 1) & 1) * STGSZ;
            const __half* qsrc = qh + (size_t)(t + 1) * 128;
            const __half* vsrc = vh + (size_t)(t + 1) * 128;
            #pragma unroll
            for (int i = 0; i < 4; ++i) {
                int c = cc + i * 16;
                CP16(so + c * STR + jc * 16, qsrc + (size_t)c * NSEQ + jc * 8);
                CP16(so + STGV + c * STR + jc * 16, vsrc + (size_t)c * NSEQ + jc * 8);
            }
            CP_COMMIT();
        }

        // ---- 4 chunks of 16 m-cols (this warp's m-half): G1 -> exp -> G2 ----
        #pragma unroll
        for (int mp = 0; mp < 4; ++mp) {
            // G1: s[nb][mt][4] over 16 m-cols, reduce c via 4 k16 steps
            float s[2][2][4];
            #pragma unroll
            for (int nb = 0; nb < 2; ++nb)
                #pragma unroll
                for (int mt = 0; mt < 2; ++mt)
                    #pragma unroll
                    for (int e = 0; e < 4; ++e) s[nb][mt][e] = 0.f;

            #pragma unroll
            for (int kk = 0; kk < 4; ++kk) {
                uint32_t ka0, ka1, ka2, ka3, kb0, kb1, kb2, kb3;
                LDSM4T(ka0, ka1, ka2, ka3, kaddr + kk * 16 * STR);        // nb=0
                LDSM4T(kb0, kb1, kb2, kb3, kaddr + kk * 16 * STR + 32);   // nb=1
                uint32_t q0, q1, q2, q3;
                LDSM4T(q0, q1, q2, q3, qs + qbase + kk * 16 * STR + mp * 32);
                MMA16(s[0][0], ka0, ka1, ka2, ka3, q0, q1);
                MMA16(s[0][1], ka0, ka1, ka2, ka3, q2, q3);
                MMA16(s[1][0], kb0, kb1, kb2, kb3, q0, q1);
                MMA16(s[1][1], kb0, kb1, kb2, kb3, q2, q3);
            }

            // exp: P = 2^S (pkh2 + ex2.f16x2); rowsum += P x ones
            uint32_t a[2][4];
            #pragma unroll
            for (int nb = 0; nb < 2; ++nb) {
                a[nb][0] = ex2h2(pkh2(s[nb][0][0], s[nb][0][1]));
                a[nb][1] = ex2h2(pkh2(s[nb][0][2], s[nb][0][3]));
                a[nb][2] = ex2h2(pkh2(s[nb][1][0], s[nb][1][1]));
                a[nb][3] = ex2h2(pkh2(s[nb][1][2], s[nb][1][3]));
                MMA16(ors[nb], a[nb][0], a[nb][1], a[nb][2], a[nb][3], ONES2, ONES2);
            }

            // G2: O += P_chunk x V_chunk^T
            #pragma unroll
            for (int ct = 0; ct < 4; ++ct) {
                uint32_t v0, v1, v2, v3;
                LDSM4(v0, v1, v2, v3, vs + vbase + ct * 16 * STR + mp * 32);
                #pragma unroll
                for (int nb = 0; nb < 2; ++nb) {
                    MMA16(o[nb][2 * ct],     a[nb][0], a[nb][1], a[nb][2], a[nb][3], v0, v1);
                    MMA16(o[nb][2 * ct + 1], a[nb][0], a[nb][1], a[nb][2], a[nb][3], v2, v3);
                }
            }
        }
    }

    __syncthreads();   // tile smem dead -> Os [c=64][n=128] + RS [2][128]

    // ---- rowsum partials (all tig lanes hold same value; tig==0 writes) ----
    float* RS = (float*)(smem + RSOFF);
    if (tig == 0) {
        #pragma unroll
        for (int nb = 0; nb < 2; ++nb) {
            RS[wm * 128 + nw0 + nb * 16 + g]     = ors[nb][0];
            RS[wm * 128 + nw0 + nb * 16 + 8 + g] = ors[nb][2];
        }
    }

    // ---- combine O partials: wm=0 stores, wm=1 adds ----
    if (wm == 0) {
        #pragma unroll
        for (int nb = 0; nb < 2; ++nb)
            #pragma unroll
            for (int ct = 0; ct < 8; ++ct)
                #pragma unroll
                for (int e = 0; e < 4; ++e) {
                    int c = 8 * ct + 2 * tig + (e & 1);
                    int n = nw0 + nb * 16 + g + 8 * (e >> 1);
                    *(float*)(smem + c * OSTB + n * 4) = o[nb][ct][e];
                }
    }
    __syncthreads();
    if (wm == 1) {
        #pragma unroll
        for (int nb = 0; nb < 2; ++nb)
            #pragma unroll
            for (int ct = 0; ct < 8; ++ct)
                #pragma unroll
                for (int e = 0; e < 4; ++e) {
                    int c = 8 * ct + 2 * tig + (e & 1);
                    int n = nw0 + nb * 16 + g + 8 * (e >> 1);
                    float* p = (float*)(smem + c * OSTB + n * 4);
                    *p = *p + o[nb][ct][e];
                }
    }
    __syncthreads();

    // ---- inverse total rowsum into RS[0..127] ----
    if (tid < 128) RS[tid] = 1.f / (RS[tid] + RS[128 + tid]);
    __syncthreads();

    // ---- normalize + coalesced vectorized store ----
    #pragma unroll
    for (int i = 0; i < 8; ++i) {
        int flat = i * 256 + tid;
        int c = flat >> 5, nq = flat & 31;
        float4 v  = *(const float4*)(smem + c * OSTB + nq * 16);
        float4 iv = *(const float4*)(RS + nq * 4);
        v.x *= iv.x; v.y *= iv.y; v.z *= iv.z; v.w *= iv.w;
        *(float4*)(Out + base + (size_t)c * NSEQ + n0 + nq * 4) = v;
    }
}

extern "C" void kernel_launch(void* const* d_in, const int* in_sizes, int n_in,
                              void* d_out, int out_size)
{
    const float* k = (const float*)d_in[0];
    const float* q = (const float*)d_in[1];
    const float* v = (const float*)d_in[2];
    float* out = (float*)d_out;

    dim3 gcvt(TOT / (256 * 8), 3);
    cvt_to_f16<<<gcvt, 256>>>(k, q, v);

    cudaFuncSetAttribute(attn_mma_v9, cudaFuncAttributeMaxDynamicSharedMemorySize, SMEM_TOTAL);
    dim3 grid(NSEQ / 128, 8);          // 32 x 8 = 256 CTAs, 2 per SM
    attn_mma_v9<<<grid, 256, SMEM_TOTAL>>>(out);
}

// round 15
// speedup vs baseline: 1.2335x; 1.2335x over previous
#include <cuda_runtime.h>
#include <cuda_fp16.h>
#include <cstdint>
#include <math.h>

// SelfAttention B=8, C=64, N=4096 fp32. v10 = v7 (best, 111us) with the tile
// pipeline relaxed: 4 smem stages, tiles processed in GROUPS OF 2 with one
// CP_WAIT(0)+__syncthreads per group (16 barriers vs 32). Compute body,
// layouts, register tiling identical to v7 (verified).
//  - fp16 m16n8k16 + ldmatrix; fp16 globals, K pre-scaled by 0.125*log2e
//  - softmax: pkh2 + ex2.f16x2 ; rowsum via ones-column MMA
//  - 32 n-rows/warp (K fragments register-resident), 1 CTA/SM, 254 regs

#define NSEQ 4096
#define CD   64
#define TOT  (8 * CD * NSEQ)

#define KSB  528               // K row stride bytes (256 n * 2B + 16)
#define STR  272               // Q/V row stride bytes (128 m * 2B + 16)
#define OFF_KS 0               // K [c=64][n=256] fp16, 33792 B
#define STG0   33792           // 4 stages, each Q(17408)+V(17408)
#define STGSZ  34816
#define STGV   17408
#define SMEM_TOTAL 173056      // 33792 + 4*34816
#define OSTB   1040            // epilogue fp32 O staging stride (offset 0)

#define ONES2 0x3C003C00u      // f16x2 {1.0, 1.0}

__device__ __align__(16) __half gK[TOT];
__device__ __align__(16) __half gQ[TOT];
__device__ __align__(16) __half gV[TOT];

static __device__ __forceinline__ uint32_t smem_u32(const void* p) {
    uint32_t a;
    asm("{ .reg .u64 t; cvta.to.shared.u64 t, %1; cvt.u32.u64 %0, t; }" : "=r"(a) : "l"(p));
    return a;
}
static __device__ __forceinline__ uint32_t pkh2(float lo, float hi) {
    uint32_t d;
    asm("cvt.rn.f16x2.f32 %0, %1, %2;" : "=r"(d) : "f"(hi), "f"(lo));
    return d;
}
static __device__ __forceinline__ uint32_t ex2h2(uint32_t x) {
    uint32_t d;
    asm("ex2.approx.f16x2 %0, %1;" : "=r"(d) : "r"(x));
    return d;
}

#define CP16(dst, src) asm volatile("cp.async.cg.shared.global [%0], [%1], 16;" :: "r"(dst), "l"(src) : "memory")
#define CP_COMMIT()    asm volatile("cp.async.commit_group;" ::: "memory")
#define CP_WAIT(n)     asm volatile("cp.async.wait_group %0;" :: "n"(n) : "memory")

#define LDSM4(r0,r1,r2,r3,a) \
    asm volatile("ldmatrix.sync.aligned.m8n8.x4.shared.b16 {%0,%1,%2,%3}, [%4];" \
        : "=r"(r0),"=r"(r1),"=r"(r2),"=r"(r3) : "r"(a))
#define LDSM4T(r0,r1,r2,r3,a) \
    asm volatile("ldmatrix.sync.aligned.m8n8.x4.trans.shared.b16 {%0,%1,%2,%3}, [%4];" \
        : "=r"(r0),"=r"(r1),"=r"(r2),"=r"(r3) : "r"(a))

#define MMA16(d, a0, a1, a2, a3, b0, b1)                                         \
    asm volatile("mma.sync.aligned.m16n8k16.row.col.f32.f16.f16.f32 "            \
        "{%0,%1,%2,%3}, {%4,%5,%6,%7}, {%8,%9}, {%0,%1,%2,%3};"                  \
        : "+f"((d)[0]), "+f"((d)[1]), "+f"((d)[2]), "+f"((d)[3])                 \
        : "r"(a0), "r"(a1), "r"(a2), "r"(a3), "r"(b0), "r"(b1))

// ---- kernel 1: fp32 -> fp16 (K pre-scaled by 0.125*log2 e) ----
__global__ __launch_bounds__(256)
void cvt_to_f16(const float* __restrict__ K, const float* __restrict__ Q,
                const float* __restrict__ V)
{
    const int i = (blockIdx.x * 256 + threadIdx.x) * 8;
    const float sc = (blockIdx.y == 0) ? 0.18033688011112042f : 1.0f;
    const float* src = (blockIdx.y == 0) ? K : (blockIdx.y == 1) ? Q : V;
    __half* dst = (blockIdx.y == 0) ? gK : (blockIdx.y == 1) ? gQ : gV;
    float4 a = *(const float4*)(src + i);
    float4 b = *(const float4*)(src + i + 4);
    *(uint4*)(dst + i) = make_uint4(pkh2(a.x * sc, a.y * sc), pkh2(a.z * sc, a.w * sc),
                                    pkh2(b.x * sc, b.y * sc), pkh2(b.z * sc, b.w * sc));
}

// ---- kernel 2: attention ----
__global__ __launch_bounds__(256, 1)
void attn_mma_v10(float* __restrict__ Out)
{
    extern __shared__ char smem[];
    const uint32_t sb = smem_u32(smem);
    const int tid  = threadIdx.x;
    const int wid  = tid >> 5, lane = tid & 31;
    const int g    = lane >> 2, tig = lane & 3;
    const int nw0  = wid * 32;                  // warp's 32-row block in CTA
    const int b    = blockIdx.y, n0 = blockIdx.x * 256;
    const size_t base = (size_t)b * CD * NSEQ;
    const __half* kh = gK + base;
    const __half* qh = gQ + base;
    const __half* vh = gV + base;

    const int cc = tid >> 4, jc = tid & 15;     // Q/V loader lanes

    // ---- prologue: group 0 = K tile [c=64][n=256] + tile 0 Q/V ----
    #pragma unroll
    for (int i = 0; i < 8; ++i) {
        int flat = i * 256 + tid, c = flat >> 5, j = flat & 31;
        CP16(sb + OFF_KS + c * KSB + j * 16, kh + (size_t)c * NSEQ + n0 + j * 8);
    }
    #pragma unroll
    for (int i = 0; i < 4; ++i) {
        int c = cc + i * 16;
        CP16(sb + STG0 + c * STR + jc * 16, qh + (size_t)c * NSEQ + jc * 8);
        CP16(sb + STG0 + STGV + c * STR + jc * 16, vh + (size_t)c * NSEQ + jc * 8);
    }
    CP_COMMIT();
    // group 1: tile 1 into stage 1
    #pragma unroll
    for (int i = 0; i < 4; ++i) {
        int c = cc + i * 16;
        CP16(sb + STG0 + STGSZ + c * STR + jc * 16, qh + (size_t)c * NSEQ + 128 + jc * 8);
        CP16(sb + STG0 + STGSZ + STGV + c * STR + jc * 16, vh + (size_t)c * NSEQ + 128 + jc * 8);
    }
    CP_COMMIT();

    float o[2][8][4];                // O: [nblk][ct][frag]
    float ors[2][4];                 // rowsum via ones-MMA: [nblk][frag]
    #pragma unroll
    for (int nb = 0; nb < 2; ++nb) {
        #pragma unroll
        for (int e = 0; e < 4; ++e) ors[nb][e] = 0.f;
        #pragma unroll
        for (int ct = 0; ct < 8; ++ct)
            #pragma unroll
            for (int e = 0; e < 4; ++e) o[nb][ct][e] = 0.f;
    }

    const uint32_t kaddr = sb + OFF_KS + ((lane & 7) + ((lane & 16) ? 8 : 0)) * KSB
                         + (nw0 + ((lane & 8) ? 8 : 0)) * 2;
    const uint32_t qbase = ((lane & 7) + ((lane & 8) ? 8 : 0)) * STR
                         + ((lane & 16) ? 16 : 0);
    const uint32_t vbase = ((lane & 7) + ((lane & 16) ? 8 : 0)) * STR
                         + ((lane & 8) ? 16 : 0);

    CP_WAIT(1);            // group 0 (K + tile 0) landed
    __syncthreads();

    // K A-fragments: [nblk][kk][4], constant across all tiles (32 regs)
    // A blocks at n = nw0, nw0+16 -> byte offset nb*32
    uint32_t ak[2][4][4];
    #pragma unroll
    for (int nb = 0; nb < 2; ++nb)
        #pragma unroll
        for (int kk = 0; kk < 4; ++kk)
            LDSM4T(ak[nb][kk][0], ak[nb][kk][1], ak[nb][kk][2], ak[nb][kk][3],
                   kaddr + nb * 32 + kk * 16 * KSB);

    for (int grp = 0; grp < 16; ++grp) {
        const int t0 = grp * 2;

        // one wait+barrier per 2 tiles: retire ALL pending copies, publish
        if (grp > 0) { CP_WAIT(0); __syncthreads(); }

        if (t0 + 2 < 32) {           // prefetch tiles t0+2, t0+3 (one group)
            #pragma unroll
            for (int pf = 0; pf < 2; ++pf) {
                const int tp = t0 + 2 + pf;
                const uint32_t so = sb + STG0 + (uint32_t)(tp & 3) * STGSZ;
                const __half* qsrc = qh + (size_t)tp * 128;
                const __half* vsrc = vh + (size_t)tp * 128;
                #pragma unroll
                for (int i = 0; i < 4; ++i) {
                    int c = cc + i * 16;
                    CP16(so + c * STR + jc * 16, qsrc + (size_t)c * NSEQ + jc * 8);
                    CP16(so + STGV + c * STR + jc * 16, vsrc + (size_t)c * NSEQ + jc * 8);
                }
            }
            CP_COMMIT();
        }

        #pragma unroll
        for (int tt = 0; tt < 2; ++tt) {
            const uint32_t stg = sb + STG0 + (uint32_t)((t0 + tt) & 3) * STGSZ;
            const uint32_t qs = stg, vs = stg + STGV;

            #pragma unroll
            for (int h = 0; h < 2; ++h) {
                const uint32_t hoff = h * 128;

                // ---- GEMM1: S[32n][64m] = (c*K)^T x Q ----
                float s[2][8][4];
                #pragma unroll
                for (int nb = 0; nb < 2; ++nb)
                    #pragma unroll
                    for (int mt = 0; mt < 8; ++mt)
                        #pragma unroll
                        for (int e = 0; e < 4; ++e) s[nb][mt][e] = 0.f;

                #pragma unroll
                for (int mp = 0; mp < 4; ++mp)
                    #pragma unroll
                    for (int kk = 0; kk < 4; ++kk) {
                        uint32_t b0, b1, b2, b3;
                        LDSM4T(b0, b1, b2, b3, qs + qbase + kk * 16 * STR + hoff + mp * 32);
                        #pragma unroll
                        for (int nb = 0; nb < 2; ++nb) {
                            MMA16(s[nb][2 * mp],     ak[nb][kk][0], ak[nb][kk][1], ak[nb][kk][2], ak[nb][kk][3], b0, b1);
                            MMA16(s[nb][2 * mp + 1], ak[nb][kk][0], ak[nb][kk][1], ak[nb][kk][2], ak[nb][kk][3], b2, b3);
                        }
                    }

                // ---- P = 2^S (pkh2 + ex2.f16x2); O += P x V^T; rowsum += P x 1 ----
                #pragma unroll
                for (int kk = 0; kk < 4; ++kk) {
                    uint32_t a[2][4];
                    #pragma unroll
                    for (int nb = 0; nb < 2; ++nb) {
                        a[nb][0] = ex2h2(pkh2(s[nb][2 * kk][0],     s[nb][2 * kk][1]));
                        a[nb][1] = ex2h2(pkh2(s[nb][2 * kk][2],     s[nb][2 * kk][3]));
                        a[nb][2] = ex2h2(pkh2(s[nb][2 * kk + 1][0], s[nb][2 * kk + 1][1]));
                        a[nb][3] = ex2h2(pkh2(s[nb][2 * kk + 1][2], s[nb][2 * kk + 1][3]));
                        MMA16(ors[nb], a[nb][0], a[nb][1], a[nb][2], a[nb][3], ONES2, ONES2);
                    }
                    #pragma unroll
                    for (int ct = 0; ct < 4; ++ct) {
                        uint32_t b0, b1, b2, b3;
                        LDSM4(b0, b1, b2, b3, vs + vbase + ct * 16 * STR + hoff + kk * 32);
                        #pragma unroll
                        for (int nb = 0; nb < 2; ++nb) {
                            MMA16(o[nb][2 * ct],     a[nb][0], a[nb][1], a[nb][2], a[nb][3], b0, b1);
                            MMA16(o[nb][2 * ct + 1], a[nb][0], a[nb][1], a[nb][2], a[nb][3], b2, b3);
                        }
                    }
                }
            }
        }
    }

    // per-lane row sums: ors[nb][0] = row nw0+nb*16+g, ors[nb][2] = +8
    float inv[2][2];
    #pragma unroll
    for (int nb = 0; nb < 2; ++nb) {
        inv[nb][0] = 1.f / ors[nb][0];
        inv[nb][1] = 1.f / ors[nb][2];
    }

    __syncthreads();   // tile smem dead -> O staging [c=64][n=256] stride OSTB

    #pragma unroll
    for (int nb = 0; nb < 2; ++nb)
        #pragma unroll
        for (int ct = 0; ct < 8; ++ct)
            #pragma unroll
            for (int e = 0; e < 4; ++e) {
                int c = 8 * ct + 2 * tig + (e & 1);
                int n = nw0 + nb * 16 + g + 8 * (e >> 1);
                *(float*)(smem + c * OSTB + n * 4) = o[nb][ct][e] * inv[nb][e >> 1];
            }
    __syncthreads();

    // coalesced vectorized store: 64 c-rows x 64 float4
    #pragma unroll
    for (int i = 0; i < 16; ++i) {
        int flat = i * 256 + tid;
        int c = flat >> 6, nq = flat & 63;
        float4 v = *(const float4*)(smem + c * OSTB + nq * 16);
        *(float4*)(Out + base + (size_t)c * NSEQ + n0 + nq * 4) = v;
    }
}

extern "C" void kernel_launch(void* const* d_in, const int* in_sizes, int n_in,
                              void* d_out, int out_size)
{
    const float* k = (const float*)d_in[0];
    const float* q = (const float*)d_in[1];
    const float* v = (const float*)d_in[2];
    float* out = (float*)d_out;

    dim3 gcvt(TOT / (256 * 8), 3);
    cvt_to_f16<<<gcvt, 256>>>(k, q, v);

    cudaFuncSetAttribute(attn_mma_v10, cudaFuncAttributeMaxDynamicSharedMemorySize, SMEM_TOTAL);
    dim3 grid(NSEQ / 256, 8);          // 16 x 8 = 128 CTAs, 1 per SM
    attn_mma_v10<<<grid, 256, SMEM_TOTAL>>>(out);
}

// round 16
// speedup vs baseline: 1.2573x; 1.0193x over previous
#include <cuda_runtime.h>
#include <cuda_fp16.h>
#include <cstdint>
#include <math.h>

// SelfAttention B=8, C=64, N=4096 fp32. v11 = v10 (best, 106.5us) with GEMM1
// switched to f16 accumulators: mma m16n8k16 f16.f16.f16.f16 D-regs are
// ALREADY the f16x2 A-fragment pairs GEMM2 needs -> all 32 pkh2/half deleted,
// exp chain shortened, S registers halved (64->32) giving ptxas slack at the
// 254-reg wall. Scores accumulate in f16 (pre-scaled by 0.125*log2e; sd<=1.5,
// noise ~1e-3 log2 -> negligible after softmax averaging & num/den cancel).
// Pipeline/layout/epilogue identical to v10.

#define NSEQ 4096
#define CD   64
#define TOT  (8 * CD * NSEQ)

#define KSB  528               // K row stride bytes (256 n * 2B + 16)
#define STR  272               // Q/V row stride bytes (128 m * 2B + 16)
#define OFF_KS 0               // K [c=64][n=256] fp16, 33792 B
#define STG0   33792           // 4 stages, each Q(17408)+V(17408)
#define STGSZ  34816
#define STGV   17408
#define SMEM_TOTAL 173056      // 33792 + 4*34816
#define OSTB   1040            // epilogue fp32 O staging stride (offset 0)

#define ONES2 0x3C003C00u      // f16x2 {1.0, 1.0}

__device__ __align__(16) __half gK[TOT];
__device__ __align__(16) __half gQ[TOT];
__device__ __align__(16) __half gV[TOT];

static __device__ __forceinline__ uint32_t smem_u32(const void* p) {
    uint32_t a;
    asm("{ .reg .u64 t; cvta.to.shared.u64 t, %1; cvt.u32.u64 %0, t; }" : "=r"(a) : "l"(p));
    return a;
}
static __device__ __forceinline__ uint32_t pkh2(float lo, float hi) {
    uint32_t d;
    asm("cvt.rn.f16x2.f32 %0, %1, %2;" : "=r"(d) : "f"(hi), "f"(lo));
    return d;
}
static __device__ __forceinline__ uint32_t ex2h2(uint32_t x) {
    uint32_t d;
    asm("ex2.approx.f16x2 %0, %1;" : "=r"(d) : "r"(x));
    return d;
}

#define CP16(dst, src) asm volatile("cp.async.cg.shared.global [%0], [%1], 16;" :: "r"(dst), "l"(src) : "memory")
#define CP_COMMIT()    asm volatile("cp.async.commit_group;" ::: "memory")
#define CP_WAIT(n)     asm volatile("cp.async.wait_group %0;" :: "n"(n) : "memory")

#define LDSM4(r0,r1,r2,r3,a) \
    asm volatile("ldmatrix.sync.aligned.m8n8.x4.shared.b16 {%0,%1,%2,%3}, [%4];" \
        : "=r"(r0),"=r"(r1),"=r"(r2),"=r"(r3) : "r"(a))
#define LDSM4T(r0,r1,r2,r3,a) \
    asm volatile("ldmatrix.sync.aligned.m8n8.x4.trans.shared.b16 {%0,%1,%2,%3}, [%4];" \
        : "=r"(r0),"=r"(r1),"=r"(r2),"=r"(r3) : "r"(a))

// fp32-accumulator MMA (GEMM2 / rowsum)
#define MMA16(d, a0, a1, a2, a3, b0, b1)                                         \
    asm volatile("mma.sync.aligned.m16n8k16.row.col.f32.f16.f16.f32 "            \
        "{%0,%1,%2,%3}, {%4,%5,%6,%7}, {%8,%9}, {%0,%1,%2,%3};"                  \
        : "+f"((d)[0]), "+f"((d)[1]), "+f"((d)[2]), "+f"((d)[3])                 \
        : "r"(a0), "r"(a1), "r"(a2), "r"(a3), "r"(b0), "r"(b1))

// f16-accumulator MMA (GEMM1): D = 2 x f16x2 regs
#define MMA16H(d0, d1, a0, a1, a2, a3, b0, b1)                                   \
    asm volatile("mma.sync.aligned.m16n8k16.row.col.f16.f16.f16.f16 "            \
        "{%0,%1}, {%2,%3,%4,%5}, {%6,%7}, {%0,%1};"                              \
        : "+r"(d0), "+r"(d1)                                                     \
        : "r"(a0), "r"(a1), "r"(a2), "r"(a3), "r"(b0), "r"(b1))

// ---- kernel 1: fp32 -> fp16 (K pre-scaled by 0.125*log2 e) ----
__global__ __launch_bounds__(256)
void cvt_to_f16(const float* __restrict__ K, const float* __restrict__ Q,
                const float* __restrict__ V)
{
    const int i = (blockIdx.x * 256 + threadIdx.x) * 8;
    const float sc = (blockIdx.y == 0) ? 0.18033688011112042f : 1.0f;
    const float* src = (blockIdx.y == 0) ? K : (blockIdx.y == 1) ? Q : V;
    __half* dst = (blockIdx.y == 0) ? gK : (blockIdx.y == 1) ? gQ : gV;
    float4 a = *(const float4*)(src + i);
    float4 b = *(const float4*)(src + i + 4);
    *(uint4*)(dst + i) = make_uint4(pkh2(a.x * sc, a.y * sc), pkh2(a.z * sc, a.w * sc),
                                    pkh2(b.x * sc, b.y * sc), pkh2(b.z * sc, b.w * sc));
}

// ---- kernel 2: attention ----
__global__ __launch_bounds__(256, 1)
void attn_mma_v11(float* __restrict__ Out)
{
    extern __shared__ char smem[];
    const uint32_t sb = smem_u32(smem);
    const int tid  = threadIdx.x;
    const int wid  = tid >> 5, lane = tid & 31;
    const int g    = lane >> 2, tig = lane & 3;
    const int nw0  = wid * 32;                  // warp's 32-row block in CTA
    const int b    = blockIdx.y, n0 = blockIdx.x * 256;
    const size_t base = (size_t)b * CD * NSEQ;
    const __half* kh = gK + base;
    const __half* qh = gQ + base;
    const __half* vh = gV + base;

    const int cc = tid >> 4, jc = tid & 15;     // Q/V loader lanes

    // ---- prologue: group 0 = K tile [c=64][n=256] + tile 0 Q/V ----
    #pragma unroll
    for (int i = 0; i < 8; ++i) {
        int flat = i * 256 + tid, c = flat >> 5, j = flat & 31;
        CP16(sb + OFF_KS + c * KSB + j * 16, kh + (size_t)c * NSEQ + n0 + j * 8);
    }
    #pragma unroll
    for (int i = 0; i < 4; ++i) {
        int c = cc + i * 16;
        CP16(sb + STG0 + c * STR + jc * 16, qh + (size_t)c * NSEQ + jc * 8);
        CP16(sb + STG0 + STGV + c * STR + jc * 16, vh + (size_t)c * NSEQ + jc * 8);
    }
    CP_COMMIT();
    // group 1: tile 1 into stage 1
    #pragma unroll
    for (int i = 0; i < 4; ++i) {
        int c = cc + i * 16;
        CP16(sb + STG0 + STGSZ + c * STR + jc * 16, qh + (size_t)c * NSEQ + 128 + jc * 8);
        CP16(sb + STG0 + STGSZ + STGV + c * STR + jc * 16, vh + (size_t)c * NSEQ + 128 + jc * 8);
    }
    CP_COMMIT();

    float o[2][8][4];                // O: [nblk][ct][frag] fp32
    float ors[2][4];                 // rowsum via ones-MMA (fp32)
    #pragma unroll
    for (int nb = 0; nb < 2; ++nb) {
        #pragma unroll
        for (int e = 0; e < 4; ++e) ors[nb][e] = 0.f;
        #pragma unroll
        for (int ct = 0; ct < 8; ++ct)
            #pragma unroll
            for (int e = 0; e < 4; ++e) o[nb][ct][e] = 0.f;
    }

    const uint32_t kaddr = sb + OFF_KS + ((lane & 7) + ((lane & 16) ? 8 : 0)) * KSB
                         + (nw0 + ((lane & 8) ? 8 : 0)) * 2;
    const uint32_t qbase = ((lane & 7) + ((lane & 8) ? 8 : 0)) * STR
                         + ((lane & 16) ? 16 : 0);
    const uint32_t vbase = ((lane & 7) + ((lane & 16) ? 8 : 0)) * STR
                         + ((lane & 8) ? 16 : 0);

    CP_WAIT(1);            // group 0 (K + tile 0) landed
    __syncthreads();

    // K A-fragments: [nblk][kk][4], constant across all tiles (32 regs)
    uint32_t ak[2][4][4];
    #pragma unroll
    for (int nb = 0; nb < 2; ++nb)
        #pragma unroll
        for (int kk = 0; kk < 4; ++kk)
            LDSM4T(ak[nb][kk][0], ak[nb][kk][1], ak[nb][kk][2], ak[nb][kk][3],
                   kaddr + nb * 32 + kk * 16 * KSB);

    for (int grp = 0; grp < 16; ++grp) {
        const int t0 = grp * 2;

        if (grp > 0) { CP_WAIT(0); __syncthreads(); }

        if (t0 + 2 < 32) {           // prefetch tiles t0+2, t0+3 (one group)
            #pragma unroll
            for (int pf = 0; pf < 2; ++pf) {
                const int tp = t0 + 2 + pf;
                const uint32_t so = sb + STG0 + (uint32_t)(tp & 3) * STGSZ;
                const __half* qsrc = qh + (size_t)tp * 128;
                const __half* vsrc = vh + (size_t)tp * 128;
                #pragma unroll
                for (int i = 0; i < 4; ++i) {
                    int c = cc + i * 16;
                    CP16(so + c * STR + jc * 16, qsrc + (size_t)c * NSEQ + jc * 8);
                    CP16(so + STGV + c * STR + jc * 16, vsrc + (size_t)c * NSEQ + jc * 8);
                }
            }
            CP_COMMIT();
        }

        #pragma unroll
        for (int tt = 0; tt < 2; ++tt) {
            const uint32_t stg = sb + STG0 + (uint32_t)((t0 + tt) & 3) * STGSZ;
            const uint32_t qs = stg, vs = stg + STGV;

            #pragma unroll
            for (int h = 0; h < 2; ++h) {
                const uint32_t hoff = h * 128;

                // ---- GEMM1 (f16 acc): S[32n][64m] = (c*K)^T x Q ----
                // s16[nb][mt] = {c0: row g cols 2tig..+1, c1: row g+8 cols 2tig..+1}
                uint32_t s16[2][8][2];
                #pragma unroll
                for (int nb = 0; nb < 2; ++nb)
                    #pragma unroll
                    for (int mt = 0; mt < 8; ++mt) {
                        s16[nb][mt][0] = 0u;
                        s16[nb][mt][1] = 0u;
                    }

                #pragma unroll
                for (int mp = 0; mp < 4; ++mp)
                    #pragma unroll
                    for (int kk = 0; kk < 4; ++kk) {
                        uint32_t b0, b1, b2, b3;
                        LDSM4T(b0, b1, b2, b3, qs + qbase + kk * 16 * STR + hoff + mp * 32);
                        #pragma unroll
                        for (int nb = 0; nb < 2; ++nb) {
                            MMA16H(s16[nb][2 * mp][0],     s16[nb][2 * mp][1],
                                   ak[nb][kk][0], ak[nb][kk][1], ak[nb][kk][2], ak[nb][kk][3], b0, b1);
                            MMA16H(s16[nb][2 * mp + 1][0], s16[nb][2 * mp + 1][1],
                                   ak[nb][kk][0], ak[nb][kk][1], ak[nb][kk][2], ak[nb][kk][3], b2, b3);
                        }
                    }

                // ---- P = 2^S: ex2.f16x2 directly on D regs (no pkh2) ----
                //      O += P x V^T; rowsum += P x ones
                #pragma unroll
                for (int kk = 0; kk < 4; ++kk) {
                    uint32_t a[2][4];
                    #pragma unroll
                    for (int nb = 0; nb < 2; ++nb) {
                        a[nb][0] = ex2h2(s16[nb][2 * kk][0]);       // row g,   cols 2tig..+1
                        a[nb][1] = ex2h2(s16[nb][2 * kk][1]);       // row g+8, cols 2tig..+1
                        a[nb][2] = ex2h2(s16[nb][2 * kk + 1][0]);   // row g,   cols +8
                        a[nb][3] = ex2h2(s16[nb][2 * kk + 1][1]);   // row g+8, cols +8
                        MMA16(ors[nb], a[nb][0], a[nb][1], a[nb][2], a[nb][3], ONES2, ONES2);
                    }
                    #pragma unroll
                    for (int ct = 0; ct < 4; ++ct) {
                        uint32_t b0, b1, b2, b3;
                        LDSM4(b0, b1, b2, b3, vs + vbase + ct * 16 * STR + hoff + kk * 32);
                        #pragma unroll
                        for (int nb = 0; nb < 2; ++nb) {
                            MMA16(o[nb][2 * ct],     a[nb][0], a[nb][1], a[nb][2], a[nb][3], b0, b1);
                            MMA16(o[nb][2 * ct + 1], a[nb][0], a[nb][1], a[nb][2], a[nb][3], b2, b3);
                        }
                    }
                }
            }
        }
    }

    // per-lane row sums: ors[nb][0] = row nw0+nb*16+g, ors[nb][2] = +8
    float inv[2][2];
    #pragma unroll
    for (int nb = 0; nb < 2; ++nb) {
        inv[nb][0] = 1.f / ors[nb][0];
        inv[nb][1] = 1.f / ors[nb][2];
    }

    __syncthreads();   // tile smem dead -> O staging [c=64][n=256] stride OSTB

    #pragma unroll
    for (int nb = 0; nb < 2; ++nb)
        #pragma unroll
        for (int ct = 0; ct < 8; ++ct)
            #pragma unroll
            for (int e = 0; e < 4; ++e) {
                int c = 8 * ct + 2 * tig + (e & 1);
                int n = nw0 + nb * 16 + g + 8 * (e >> 1);
                *(float*)(smem + c * OSTB + n * 4) = o[nb][ct][e] * inv[nb][e >> 1];
            }
    __syncthreads();

    // coalesced vectorized store: 64 c-rows x 64 float4
    #pragma unroll
    for (int i = 0; i < 16; ++i) {
        int flat = i * 256 + tid;
        int c = flat >> 6, nq = flat & 63;
        float4 v = *(const float4*)(smem + c * OSTB + nq * 16);
        *(float4*)(Out + base + (size_t)c * NSEQ + n0 + nq * 4) = v;
    }
}

extern "C" void kernel_launch(void* const* d_in, const int* in_sizes, int n_in,
                              void* d_out, int out_size)
{
    const float* k = (const float*)d_in[0];
    const float* q = (const float*)d_in[1];
    const float* v = (const float*)d_in[2];
    float* out = (float*)d_out;

    dim3 gcvt(TOT / (256 * 8), 3);
    cvt_to_f16<<<gcvt, 256>>>(k, q, v);

    cudaFuncSetAttribute(attn_mma_v11, cudaFuncAttributeMaxDynamicSharedMemorySize, SMEM_TOTAL);
    dim3 grid(NSEQ / 256, 8);          // 16 x 8 = 128 CTAs, 1 per SM
    attn_mma_v11<<<grid, 256, SMEM_TOTAL>>>(out);
}